// round 11
// baseline (speedup 1.0000x reference)
#include <cuda_runtime.h>
#include <cuda_bf16.h>
#include <cstdint>

// ---------------------------------------------------------------------------
// Problem constants (fixed instance: B=2048 windows, N_actual=60, C=512)
// ---------------------------------------------------------------------------
#define N_ACT    60
#define CDIM     512
#define NHEAD    16
#define HD       32
#define BWIN     2048
#define MROWS    (BWIN * N_ACT)          // 122880 = 960 * 128
#define SCALE_Q  0.1767766952966369f     // 32^-0.5

// ---------------------------------------------------------------------------
// Device scratch (static __device__ arrays: allocation-guard safe)
// ---------------------------------------------------------------------------
__device__ float g_qkvT[3 * CDIM * CDIM];            // [1536][512] W^T tf32-rounded
__device__ float g_projT[CDIM * CDIM];               // [512][512]  W^T tf32-rounded
__device__ float g_x[(size_t)MROWS * CDIM];          // [122880][512] x tf32-rounded
__device__ float g_qkv[(size_t)MROWS * 3 * CDIM];    // [122880][1536] q|k|v; q-slot -> attn out

// ---------------------------------------------------------------------------
// Helpers
// ---------------------------------------------------------------------------
__device__ __forceinline__ float tf32r(float x) {
    float y;
    asm("cvt.rna.tf32.f32 %0, %1;" : "=f"(y) : "f"(x));
    return y;
}
__device__ __forceinline__ uint32_t f2u(float x) { return __float_as_uint(x); }

__device__ __forceinline__ void mma_tf32(float c[4],
                                         float a0, float a1, float a2, float a3,
                                         float b0, float b1) {
    asm volatile(
        "mma.sync.aligned.m16n8k8.row.col.f32.tf32.tf32.f32 "
        "{%0,%1,%2,%3}, {%4,%5,%6,%7}, {%8,%9}, {%0,%1,%2,%3};\n"
        : "+f"(c[0]), "+f"(c[1]), "+f"(c[2]), "+f"(c[3])
        : "r"(f2u(a0)), "r"(f2u(a1)), "r"(f2u(a2)), "r"(f2u(a3)),
          "r"(f2u(b0)), "r"(f2u(b1)));
}

__device__ __forceinline__ uint32_t smem_u32(const void* p) {
    uint32_t a;
    asm("{ .reg .u64 t; cvta.to.shared.u64 t, %1; cvt.u32.u64 %0, t; }"
        : "=r"(a) : "l"(p));
    return a;
}

__device__ __forceinline__ void cpa16(uint32_t smem_dst, const float* gsrc) {
    asm volatile("cp.async.cg.shared.global [%0], [%1], 16;"
                 :: "r"(smem_dst), "l"(gsrc));
}
#define CPA_COMMIT() asm volatile("cp.async.commit_group;" ::: "memory")
#define CPA_WAIT1()  asm volatile("cp.async.wait_group 1;" ::: "memory")
#define CPA_WAIT0()  asm volatile("cp.async.wait_group 0;" ::: "memory")

// ---------------------------------------------------------------------------
// Kernel: tf32-round x into g_x (one float4 per thread)
// ---------------------------------------------------------------------------
__global__ void kround(const float* __restrict__ src) {
    size_t i = ((size_t)blockIdx.x * 256 + threadIdx.x) * 4;
    float4 v = *reinterpret_cast<const float4*>(src + i);
    v.x = tf32r(v.x); v.y = tf32r(v.y); v.z = tf32r(v.z); v.w = tf32r(v.w);
    *reinterpret_cast<float4*>(g_x + i) = v;
}

// ---------------------------------------------------------------------------
// Kernel 0: transpose + tf32-round weights.
// which==0: qkv_w [512][1536] -> g_qkvT[1536][512]
// which==1: proj_w [512][512] -> g_projT[512][512]
// ---------------------------------------------------------------------------
__global__ void ktranspose(const float* __restrict__ src, int R, int Ccols, int which) {
    __shared__ float tile[32][33];
    float* dst = which ? g_projT : g_qkvT;
    int cb = blockIdx.x * 32, rb = blockIdx.y * 32;
    tile[threadIdx.y][threadIdx.x] = src[(size_t)(rb + threadIdx.y) * Ccols + cb + threadIdx.x];
    __syncthreads();
    dst[(size_t)(cb + threadIdx.y) * R + rb + threadIdx.x] = tf32r(tile[threadIdx.x][threadIdx.y]);
}

// ---------------------------------------------------------------------------
// cp.async double-buffered tf32 GEMM.
// CTA tile 128x128, 128 threads (4 warps = 2m x 2n), warp tile 64x64.
// K-chunk 16, 32 chunks, 2 smem stages. Stride 20 (conflict-free).
// Static smem: 2 ops x 2 stages x 128 x 20 floats = 40960 B.
// All gmem A/B operands are pre-rounded tf32.
// mode 0: A=g_x (lda 512),  B=g_qkvT, bias=qkvb, C=g_qkv (ldc 1536),
//         q-cols scaled, output tf32-rounded.
// mode 1: A=g_qkv (lda 1536, attn out in cols 0..511, already tf32),
//         B=g_projT, bias=projb, C=out (ldc 512).
// ---------------------------------------------------------------------------
#define PST 20

__global__ __launch_bounds__(128, 2) void kgemm_pipe(const float* __restrict__ qkvb,
                                                     const float* __restrict__ projb,
                                                     float* __restrict__ out,
                                                     int mode) {
    __shared__ float sA[2][128 * PST];
    __shared__ float sB[2][128 * PST];

    const float* Aptr = mode ? g_qkv : g_x;
    const int    lda  = mode ? (3 * CDIM) : CDIM;
    const float* Bw   = mode ? g_projT : g_qkvT;
    const float* bias = mode ? projb : qkvb;
    float*       Cp   = mode ? out : g_qkv;
    const int    ldc  = mode ? CDIM : (3 * CDIM);

    const int m0 = blockIdx.y * 128;
    const int n0 = blockIdx.x * 128;
    const int tid  = threadIdx.x;
    const int lane = tid & 31;
    const int warp = tid >> 5;
    const int g = lane >> 2, t = lane & 3;
    const int wm = warp & 1;       // 2 m-stripes of 64 rows
    const int wn = warp >> 1;      // 2 n-stripes of 64 cols

    // staging map: thread -> (row srow + j*32, 16B chunk scol)
    const int srow = tid >> 2;           // 0..31
    const int scol = (tid & 3) * 4;      // float offset 0/4/8/12

    const uint32_t aSm0 = smem_u32(&sA[0][0]) + (uint32_t)(srow * PST + scol) * 4;
    const uint32_t bSm0 = smem_u32(&sB[0][0]) + (uint32_t)(srow * PST + scol) * 4;
    const float* aG = Aptr + (size_t)(m0 + srow) * lda + scol;
    const float* bG = Bw + (size_t)(n0 + srow) * CDIM + scol;

    float acc[4][8][4];
    #pragma unroll
    for (int im = 0; im < 4; im++)
        #pragma unroll
        for (int jn = 0; jn < 8; jn++)
            #pragma unroll
            for (int q = 0; q < 4; q++) acc[im][jn][q] = 0.f;

    // prefetch chunk 0 into stage 0
    #pragma unroll
    for (int j = 0; j < 4; j++) {
        cpa16(aSm0 + j * (32 * PST) * 4, aG + (size_t)(j * 32) * lda);
        cpa16(bSm0 + j * (32 * PST) * 4, bG + (size_t)(j * 32) * CDIM);
    }
    CPA_COMMIT();

    for (int kc = 0; kc < 32; kc++) {
        const int cur = kc & 1;
        if (kc < 31) {
            const int nxt = (kc + 1) & 1;
            const uint32_t stgOff = (uint32_t)(nxt * 128 * PST) * 4;
            const int kOff = (kc + 1) * 16;
            #pragma unroll
            for (int j = 0; j < 4; j++) {
                cpa16(aSm0 + stgOff + j * (32 * PST) * 4, aG + (size_t)(j * 32) * lda + kOff);
                cpa16(bSm0 + stgOff + j * (32 * PST) * 4, bG + (size_t)(j * 32) * CDIM + kOff);
            }
            CPA_COMMIT();
            CPA_WAIT1();
        } else {
            CPA_WAIT0();
        }
        __syncthreads();

        const float* cA = &sA[cur][0] + (wm * 64 + g) * PST + t;
        const float* cB = &sB[cur][0] + (wn * 64 + g) * PST + t;
        #pragma unroll
        for (int ks = 0; ks < 2; ks++) {
            const int k0 = ks * 8;
            float a[4][4];
            #pragma unroll
            for (int im = 0; im < 4; im++) {
                const float* ap = cA + im * 16 * PST + k0;
                a[im][0] = ap[0];
                a[im][1] = ap[8 * PST];
                a[im][2] = ap[4];
                a[im][3] = ap[8 * PST + 4];
            }
            float b[8][2];
            #pragma unroll
            for (int jn = 0; jn < 8; jn++) {
                const float* bp = cB + jn * 8 * PST + k0;
                b[jn][0] = bp[0];
                b[jn][1] = bp[4];
            }
            #pragma unroll
            for (int im = 0; im < 4; im++)
                #pragma unroll
                for (int jn = 0; jn < 8; jn++)
                    mma_tf32(acc[im][jn], a[im][0], a[im][1], a[im][2], a[im][3],
                             b[jn][0], b[jn][1]);
        }
        __syncthreads();
    }

    // ---- epilogue: bias (+ q-scale / tf32 round for mode 0) ----
    #pragma unroll
    for (int im = 0; im < 4; im++) {
        #pragma unroll
        for (int jn = 0; jn < 8; jn++) {
            #pragma unroll
            for (int q = 0; q < 4; q++) {
                const int row = m0 + wm * 64 + im * 16 + g + ((q >= 2) ? 8 : 0);
                const int col = n0 + wn * 64 + jn * 8 + 2 * t + (q & 1);
                float v = acc[im][jn][q] + bias[col];
                if (mode == 0) {
                    if (col < CDIM) v *= SCALE_Q;
                    Cp[(size_t)row * ldc + col] = tf32r(v);
                } else {
                    Cp[(size_t)row * ldc + col] = v;
                }
            }
        }
    }
}

// ---------------------------------------------------------------------------
// Attention kernel: one CTA per (window, head). 128 threads (4 warps).
// smem: sU holds q|k (2 x 64x40) then is reused for P (64x72) after the
// score MMA; svT (32x72) holds V transposed. 29.75 KB total.
// Output written tf32-rounded (it feeds the proj GEMM via cp.async).
// ---------------------------------------------------------------------------
__global__ __launch_bounds__(128) void k_attn() {
    __shared__ float sU[5120];        // sq = sU[0..2560), sk = sU[2560..5120); later sS
    __shared__ float svT[32 * 72];

    float* sq = sU;
    float* sk = sU + 2560;
    float* sS = sU;                   // reused after score MMA

    const int b = blockIdx.x;
    const int h = blockIdx.y;
    const int tid  = threadIdx.x;
    const int lane = tid & 31;
    const int warp = tid >> 5;
    const int g = lane >> 2, t = lane & 3;

    const float* qb = g_qkv + (size_t)b * N_ACT * (3 * CDIM) + h * HD;
    const float* kb = qb + CDIM;
    const float* vb = qb + 2 * CDIM;

    // ---- load q, k (perm-8 layout, stride 40), v transposed (stride 72) ----
    for (int i = tid; i < 64 * 8; i += 128) {
        int r = i >> 3, c4 = i & 7, cb = c4 * 4;
        float4 vq, vk, vv;
        if (r < N_ACT) {
            vq = *reinterpret_cast<const float4*>(qb + (size_t)r * (3 * CDIM) + cb);
            vk = *reinterpret_cast<const float4*>(kb + (size_t)r * (3 * CDIM) + cb);
            vv = *reinterpret_cast<const float4*>(vb + (size_t)r * (3 * CDIM) + cb);
        } else {
            vq = vk = vv = make_float4(0.f, 0.f, 0.f, 0.f);
        }
        int base = r * 40 + (cb & 24) + ((cb >> 2) & 1);
        sq[base + 0] = vq.x; sq[base + 2] = vq.y; sq[base + 4] = vq.z; sq[base + 6] = vq.w;
        sk[base + 0] = vk.x; sk[base + 2] = vk.y; sk[base + 4] = vk.z; sk[base + 6] = vk.w;
        int pr = (r & 56) + (r & 3) * 2 + ((r >> 2) & 1);   // permuted token pos
        svT[(cb + 0) * 72 + pr] = vv.x;
        svT[(cb + 1) * 72 + pr] = vv.y;
        svT[(cb + 2) * 72 + pr] = vv.z;
        svT[(cb + 3) * 72 + pr] = vv.w;
    }
    __syncthreads();

    // ---- scores S = q @ k^T : warp handles rows 16*warp..+15 ----
    float sacc[8][4];
    #pragma unroll
    for (int jn = 0; jn < 8; jn++)
        #pragma unroll
        for (int q = 0; q < 4; q++) sacc[jn][q] = 0.f;

    #pragma unroll
    for (int ks = 0; ks < 4; ks++) {
        const int k0 = ks * 8 + 2 * t;
        const float* ap = sq + (16 * warp + g) * 40 + k0;
        float2 a0 = *reinterpret_cast<const float2*>(ap);
        float2 a1 = *reinterpret_cast<const float2*>(ap + 8 * 40);
        #pragma unroll
        for (int jn = 0; jn < 8; jn++) {
            float2 bp = *reinterpret_cast<const float2*>(sk + (jn * 8 + g) * 40 + k0);
            mma_tf32(sacc[jn], a0.x, a1.x, a0.y, a1.y, bp.x, bp.y);
        }
    }

    // ---- mask + register softmax (rows r0=16w+g, r1=r0+8) ----
    float mx[2] = {-1e30f, -1e30f};
    #pragma unroll
    for (int jn = 0; jn < 8; jn++)
        #pragma unroll
        for (int q = 0; q < 4; q++) {
            int col = jn * 8 + 2 * t + (q & 1);
            float v = sacc[jn][q] + (col >= N_ACT ? -1e9f : 0.f);
            sacc[jn][q] = v;
            mx[q >> 1] = fmaxf(mx[q >> 1], v);
        }
    #pragma unroll
    for (int o = 1; o < 4; o <<= 1) {
        mx[0] = fmaxf(mx[0], __shfl_xor_sync(0xffffffffu, mx[0], o));
        mx[1] = fmaxf(mx[1], __shfl_xor_sync(0xffffffffu, mx[1], o));
    }
    float sum[2] = {0.f, 0.f};
    #pragma unroll
    for (int jn = 0; jn < 8; jn++)
        #pragma unroll
        for (int q = 0; q < 4; q++) {
            float e = __expf(sacc[jn][q] - mx[q >> 1]);
            sacc[jn][q] = e;
            sum[q >> 1] += e;
        }
    #pragma unroll
    for (int o = 1; o < 4; o <<= 1) {
        sum[0] += __shfl_xor_sync(0xffffffffu, sum[0], o);
        sum[1] += __shfl_xor_sync(0xffffffffu, sum[1], o);
    }
    const float inv0 = 1.f / sum[0], inv1 = 1.f / sum[1];

    // all warps done reading sq/sk before sS overwrites the region
    __syncthreads();

    // store P (tf32) into sS with perm-8 k layout (own-warp rows only)
    #pragma unroll
    for (int jn = 0; jn < 8; jn++)
        #pragma unroll
        for (int q = 0; q < 4; q++) {
            int col = jn * 8 + 2 * t + (q & 1);
            int row = 16 * warp + g + ((q >= 2) ? 8 : 0);
            int pc = (col & 56) + (col & 3) * 2 + ((col >> 2) & 1);
            sS[row * 72 + pc] = tf32r(sacc[jn][q] * ((q >= 2) ? inv1 : inv0));
        }
    __syncwarp();

    // ---- O = P @ V : [16 x 32] per warp, K = 64 ----
    float oacc[4][4];
    #pragma unroll
    for (int jn = 0; jn < 4; jn++)
        #pragma unroll
        for (int q = 0; q < 4; q++) oacc[jn][q] = 0.f;

    #pragma unroll
    for (int ks = 0; ks < 8; ks++) {
        const int k0 = ks * 8 + 2 * t;
        const float* ap = sS + (16 * warp + g) * 72 + k0;
        float2 a0 = *reinterpret_cast<const float2*>(ap);
        float2 a1 = *reinterpret_cast<const float2*>(ap + 8 * 72);
        #pragma unroll
        for (int jn = 0; jn < 4; jn++) {
            float2 bp = *reinterpret_cast<const float2*>(svT + (jn * 8 + g) * 72 + k0);
            mma_tf32(oacc[jn], a0.x, a1.x, a0.y, a1.y, bp.x, bp.y);
        }
    }

    // ---- write O (tf32-rounded) into q-slot of g_qkv ----
    #pragma unroll
    for (int jn = 0; jn < 4; jn++)
        #pragma unroll
        for (int q = 0; q < 4; q++) {
            int row = 16 * warp + g + ((q >= 2) ? 8 : 0);
            int col = jn * 8 + 2 * t + (q & 1);
            if (row < N_ACT)
                g_qkv[((size_t)b * N_ACT + row) * (3 * CDIM) + h * HD + col] =
                    tf32r(oacc[jn][q]);
        }
}

// ---------------------------------------------------------------------------
// Launch (static smem only; plain launches; graph-capturable)
// ---------------------------------------------------------------------------
extern "C" void kernel_launch(void* const* d_in, const int* in_sizes, int n_in,
                              void* d_out, int out_size) {
    const float *x = nullptr, *qkvw = nullptr, *qkvb = nullptr, *projw = nullptr, *projb = nullptr;
    for (int i = 0; i < n_in; i++) {
        int s = in_sizes[i];
        if (s == CDIM * 3 * CDIM)      qkvw = (const float*)d_in[i];
        else if (s == 3 * CDIM)        qkvb = (const float*)d_in[i];
        else if (s == CDIM * CDIM)     projw = (const float*)d_in[i];
        else if (s == CDIM)            projb = (const float*)d_in[i];
        else                           x = (const float*)d_in[i];
    }
    float* out = (float*)d_out;

    // pre-round x; pre-transpose + round weights
    kround<<<MROWS * CDIM / (256 * 4), 256>>>(x);
    ktranspose<<<dim3(3 * CDIM / 32, CDIM / 32), dim3(32, 32)>>>(qkvw, CDIM, 3 * CDIM, 0);
    ktranspose<<<dim3(CDIM / 32, CDIM / 32), dim3(32, 32)>>>(projw, CDIM, CDIM, 1);

    // QKV GEMM: g_qkv[122880 x 1536] = g_x @ qkv_w (+bias, q*scale, tf32)
    kgemm_pipe<<<dim3(3 * CDIM / 128, MROWS / 128), 128>>>(qkvb, projb, out, 0);

    // attention per (window, head); O (tf32) overwrites q-slot of g_qkv
    k_attn<<<dim3(BWIN, NHEAD), 128>>>();

    // proj GEMM: out[122880 x 512] = O @ proj_w + bias
    kgemm_pipe<<<dim3(CDIM / 128, MROWS / 128), 128>>>(qkvb, projb, out, 1);
}